// round 3
// baseline (speedup 1.0000x reference)
#include <cuda_runtime.h>
#include <cuda_bf16.h>
#include <math.h>
#include <cstdint>

// ---------------- problem constants ----------------
#define Bv   4
#define Tv   1024
#define Lv   12
#define Hh   12
#define Cc   768
#define TE   64
#define WTE  704      // C - TE
#define Vv   10000
#define Dd   64
#define MT   4096     // B*T rows
#define C3   2304     // 3C
#define C4   3072     // 4C

// ---------------- scratch (device globals; no allocs allowed) ----------------
__device__ float g_x  [(size_t)MT * Cc];   // residual stream
__device__ float g_h  [(size_t)MT * Cc];   // LN output
__device__ float g_qkv[(size_t)MT * C3];   // qkv projection
__device__ float g_att[(size_t)MT * Cc];   // attention output
__device__ float g_mid[(size_t)MT * C4];   // MLP hidden

// ---------------- small helpers ----------------
__device__ __forceinline__ uint32_t smaddr(const void* p) {
    uint32_t a;
    asm("{ .reg .u64 t; cvta.to.shared.u64 t, %1; cvt.u32.u64 %0, t; }"
        : "=r"(a) : "l"(p));
    return a;
}

__device__ __forceinline__ void cp16(uint32_t dst, const void* src, int bytes) {
    asm volatile("cp.async.cg.shared.global [%0], [%1], 16, %2;"
                 :: "r"(dst), "l"(src), "r"(bytes));
}

__device__ __forceinline__ void split_tf32(float x, uint32_t& h, uint32_t& l) {
    asm("cvt.rna.tf32.f32 %0, %1;" : "=r"(h) : "f"(x));
    float r = x - __uint_as_float(h);
    asm("cvt.rna.tf32.f32 %0, %1;" : "=r"(l) : "f"(r));
}

#define MMA8(d, a, b)                                                          \
    asm volatile(                                                              \
        "mma.sync.aligned.m16n8k8.row.col.f32.tf32.tf32.f32 "                  \
        "{%0,%1,%2,%3},{%4,%5,%6,%7},{%8,%9},{%0,%1,%2,%3};"                   \
        : "+f"(d[0]), "+f"(d[1]), "+f"(d[2]), "+f"(d[3])                       \
        : "r"(a[0]), "r"(a[1]), "r"(a[2]), "r"(a[3]), "r"(b[0]), "r"(b[1]))

// ---------------- embedding: x = concat(wte[idx], cos(ts*f+p)) + wpe ----------
__global__ __launch_bounds__(256) void embed_k(
    const int* __restrict__ idx, const float* __restrict__ ts,
    const float* __restrict__ wte, const float* __restrict__ freq,
    const float* __restrict__ phase, const float* __restrict__ wpe,
    float* __restrict__ x)
{
    int rowi = blockIdx.x;           // b*T + t
    int t = rowi & (Tv - 1);
    int token = idx[rowi];
    float tsv = ts[rowi];
    for (int c = threadIdx.x; c < Cc; c += 256) {
        float v;
        if (c < WTE) v = wte[(size_t)token * WTE + c];
        else {
            int e = c - WTE;
            v = cosf(tsv * freq[e] + phase[e]);
        }
        x[(size_t)rowi * Cc + c] = v + wpe[t * Cc + c];
    }
}

// ---------------- layernorm over C=768 ----------------
__global__ __launch_bounds__(256) void ln_k(
    const float* __restrict__ x, const float* __restrict__ w,
    const float* __restrict__ bseg, float* __restrict__ out)
{
    int rowi = blockIdx.x;
    const float* xr = x + (size_t)rowi * Cc;
    int t = threadIdx.x;
    float v[3];
    float s = 0.f, sq = 0.f;
#pragma unroll
    for (int i = 0; i < 3; i++) {
        v[i] = xr[t + i * 256];
        s += v[i];
        sq += v[i] * v[i];
    }
    __shared__ float red[64];
#pragma unroll
    for (int off = 16; off; off >>= 1) {
        s  += __shfl_down_sync(0xffffffffu, s, off);
        sq += __shfl_down_sync(0xffffffffu, sq, off);
    }
    int wid = t >> 5, lane = t & 31;
    if (lane == 0) { red[wid] = s; red[wid + 32] = sq; }
    __syncthreads();
    if (wid == 0) {
        s  = (lane < 8) ? red[lane] : 0.f;
        sq = (lane < 8) ? red[lane + 32] : 0.f;
#pragma unroll
        for (int off = 4; off; off >>= 1) {
            s  += __shfl_down_sync(0xffffffffu, s, off);
            sq += __shfl_down_sync(0xffffffffu, sq, off);
        }
        if (lane == 0) {
            float mu = s * (1.f / Cc);
            float var = sq * (1.f / Cc) - mu * mu;
            red[0] = mu;
            red[1] = rsqrtf(var + 1e-5f);
        }
    }
    __syncthreads();
    float mu = red[0], rstd = red[1];
#pragma unroll
    for (int i = 0; i < 3; i++) {
        int c = t + i * 256;
        out[(size_t)rowi * Cc + c] = (v[i] - mu) * rstd * w[c] + bseg[c];
    }
}

// ---------------- tf32x3 tensor-core GEMM: out[M,N] = A[M,K] @ W[N,K]^T (+epi)
// EPI: 0 = none, 1 = +bias, 2 = +bias+residual, 3 = +bias then exact GELU
// Block tile 128x128, K-chunk 16, 256 threads = 8 warps in 2(M) x 4(N),
// warp tile 64x32 = 4 m16-tiles x 4 n8-tiles. cp.async double buffer.
// smem row stride 20 floats -> fragment LDS is bank-conflict-free.
#define SROW 20

template <int EPI>
__global__ __launch_bounds__(256, 1) void gemm_mma(
    const float* __restrict__ A, const float* __restrict__ W,
    const float* __restrict__ bias, const float* __restrict__ resid,
    float* __restrict__ out, int M, int N, int K)
{
    __shared__ float sA[2][128 * SROW];
    __shared__ float sB[2][128 * SROW];
    int tid  = threadIdx.x;
    int warp = tid >> 5, lane = tid & 31;
    int warpM = warp >> 2, warpN = warp & 3;   // 2 x 4 warps
    int grp = lane >> 2, tig = lane & 3;
    int m0 = blockIdx.y * 128, n0 = blockIdx.x * 128;

    float acc[4][4][4];
#pragma unroll
    for (int i = 0; i < 4; i++)
#pragma unroll
        for (int j = 0; j < 4; j++)
#pragma unroll
            for (int r = 0; r < 4; r++) acc[i][j][r] = 0.f;

    int nC = K >> 4;   // K-chunks of 16

    // ---- stage chunk 0 ----
    {
        uint32_t da = smaddr(&sA[0][0]);
        uint32_t db = smaddr(&sB[0][0]);
#pragma unroll
        for (int j = 0; j < 2; j++) {
            int idx = tid + j * 256;
            int r = idx >> 2, kq = (idx & 3) * 4;
            cp16(da + (r * SROW + kq) * 4,
                 A + (size_t)(m0 + r) * K + kq, 16);
            int n = n0 + r;
            const float* src = W + (size_t)(n < N ? n : N - 1) * K + kq;
            cp16(db + (r * SROW + kq) * 4, src, n < N ? 16 : 0);
        }
        asm volatile("cp.async.commit_group;");
    }

    for (int c = 0; c < nC; ++c) {
        asm volatile("cp.async.wait_group 0;");
        __syncthreads();
        if (c + 1 < nC) {
            int k0 = (c + 1) << 4;
            int buf = (c + 1) & 1;
            uint32_t da = smaddr(&sA[buf][0]);
            uint32_t db = smaddr(&sB[buf][0]);
#pragma unroll
            for (int j = 0; j < 2; j++) {
                int idx = tid + j * 256;
                int r = idx >> 2, kq = (idx & 3) * 4;
                cp16(da + (r * SROW + kq) * 4,
                     A + (size_t)(m0 + r) * K + k0 + kq, 16);
                int n = n0 + r;
                const float* src = W + (size_t)(n < N ? n : N - 1) * K + k0 + kq;
                cp16(db + (r * SROW + kq) * 4, src, n < N ? 16 : 0);
            }
            asm volatile("cp.async.commit_group;");
        }
        const float* As = sA[c & 1];
        const float* Bs = sB[c & 1];
#pragma unroll
        for (int ks = 0; ks < 2; ks++) {
            int kb = ks * 8;
            uint32_t ah[4][4], al[4][4], bh[4][2], bl[4][2];
#pragma unroll
            for (int nt = 0; nt < 4; nt++) {
                int n = warpN * 32 + nt * 8 + grp;
                split_tf32(Bs[n * SROW + kb + tig],     bh[nt][0], bl[nt][0]);
                split_tf32(Bs[n * SROW + kb + tig + 4], bh[nt][1], bl[nt][1]);
            }
#pragma unroll
            for (int mt = 0; mt < 4; mt++) {
                int m = warpM * 64 + mt * 16 + grp;
                split_tf32(As[m * SROW + kb + tig],           ah[mt][0], al[mt][0]);
                split_tf32(As[(m + 8) * SROW + kb + tig],     ah[mt][1], al[mt][1]);
                split_tf32(As[m * SROW + kb + tig + 4],       ah[mt][2], al[mt][2]);
                split_tf32(As[(m + 8) * SROW + kb + tig + 4], ah[mt][3], al[mt][3]);
            }
#pragma unroll
            for (int mt = 0; mt < 4; mt++)
#pragma unroll
                for (int nt = 0; nt < 4; nt++) {
                    MMA8(acc[mt][nt], ah[mt], bh[nt]);
                    MMA8(acc[mt][nt], ah[mt], bl[nt]);
                    MMA8(acc[mt][nt], al[mt], bh[nt]);
                }
        }
    }

    // ---- epilogue ----
#pragma unroll
    for (int mt = 0; mt < 4; mt++) {
        int row = m0 + warpM * 64 + mt * 16 + grp;
#pragma unroll
        for (int nt = 0; nt < 4; nt++) {
            int col = n0 + warpN * 32 + nt * 8 + tig * 2;
#pragma unroll
            for (int r = 0; r < 4; r++) {
                int mm = row + (r >= 2 ? 8 : 0);
                int nn = col + (r & 1);
                if (nn >= N) continue;
                float v = acc[mt][nt][r];
                if (EPI >= 1) v += bias[nn];
                if (EPI == 2) v += resid[(size_t)mm * N + nn];
                if (EPI == 3) v = 0.5f * v * (1.0f + erff(v * 0.70710678118f));
                out[(size_t)mm * N + nn] = v;
            }
        }
    }
}

// ---------------- fused causal flash attention ----------------
// grid: (T/128, B*H), block: 128 threads; one query per thread.
// Scores kept in log2 domain: q is pre-scaled by scale*log2(e), so each key
// costs exactly one exp2f (MUFU) and the rescale branch one more.
__global__ __launch_bounds__(128) void attn_k(
    const float* __restrict__ qkv, float* __restrict__ y)
{
    int bh = blockIdx.y;
    int b = bh / Hh, h = bh % Hh;
    int q0 = blockIdx.x * 128;
    int qi = q0 + threadIdx.x;
    __shared__ float Ks[64][64];
    __shared__ float Vs[64][64];
    const float qscale = 0.125f * 1.4426950408889634f;   // (1/sqrt(64)) * log2(e)

    float q[64];
    const float* qrow = &qkv[(size_t)(b * Tv + qi) * C3 + h * Dd];
#pragma unroll
    for (int i = 0; i < 16; i++) {
        float4 v = *(const float4*)&qrow[i * 4];
        q[i*4]   = v.x * qscale; q[i*4+1] = v.y * qscale;
        q[i*4+2] = v.z * qscale; q[i*4+3] = v.w * qscale;
    }
    float o[64];
#pragma unroll
    for (int d = 0; d < 64; d++) o[d] = 0.f;
    float mx = -1e30f, l = 0.f;

    int jmax = (q0 + 127) >> 6;            // inclusive key-tile bound
    int row = threadIdx.x >> 1, half = (threadIdx.x & 1) * 32;

    for (int j = 0; j <= jmax; j++) {
        const float* kbase = &qkv[(size_t)(b * Tv + j * 64 + row) * C3 + Cc + h * Dd + half];
        const float* vbase = kbase + Cc;   // V is one C further
#pragma unroll
        for (int i = 0; i < 8; i++) {
            *(float4*)&Ks[row][half + i * 4] = *(const float4*)&kbase[i * 4];
            *(float4*)&Vs[row][half + i * 4] = *(const float4*)&vbase[i * 4];
        }
        __syncthreads();
        int kend = min(64, qi - j * 64 + 1);   // causal limit inside tile
        for (int kk = 0; kk < kend; kk++) {
            float s = 0.f;
#pragma unroll
            for (int i = 0; i < 16; i++) {
                float4 kv = *(const float4*)&Ks[kk][i * 4];
                s += q[i*4] * kv.x + q[i*4+1] * kv.y + q[i*4+2] * kv.z + q[i*4+3] * kv.w;
            }
            // s is in log2 domain
            if (s > mx) {
                float c = exp2f(mx - s);
                mx = s;
                l *= c;
#pragma unroll
                for (int d = 0; d < 64; d++) o[d] *= c;
            }
            float p = exp2f(s - mx);
            l += p;
#pragma unroll
            for (int i = 0; i < 16; i++) {
                float4 vv = *(const float4*)&Vs[kk][i * 4];
                o[i*4]   += p * vv.x; o[i*4+1] += p * vv.y;
                o[i*4+2] += p * vv.z; o[i*4+3] += p * vv.w;
            }
        }
        __syncthreads();
    }
    float inv = 1.f / l;
    float* orow = &y[(size_t)(b * Tv + qi) * Cc + h * Dd];
#pragma unroll
    for (int d = 0; d < 64; d++) orow[d] = o[d] * inv;
}

// ---------------- tpred: out[m] = dot(h[m,:], tp_w) ----------------
__global__ __launch_bounds__(256) void tpred_k(
    const float* __restrict__ hbuf, const float* __restrict__ tpw,
    float* __restrict__ out)
{
    int rowi = blockIdx.x * 8 + (threadIdx.x >> 5);
    int lane = threadIdx.x & 31;
    const float* xr = hbuf + (size_t)rowi * Cc;
    float s = 0.f;
#pragma unroll
    for (int i = lane; i < Cc; i += 32) s += xr[i] * tpw[i];
#pragma unroll
    for (int off = 16; off; off >>= 1) s += __shfl_down_sync(0xffffffffu, s, off);
    if (lane == 0) out[rowi] = s;
}

// ---------------- launch ----------------
extern "C" void kernel_launch(void* const* d_in, const int* in_sizes, int n_in,
                              void* d_out, int out_size)
{
    (void)in_sizes; (void)n_in; (void)out_size;
    const int*   idx   = (const int*)  d_in[0];
    const float* ts    = (const float*)d_in[1];
    const float* wte   = (const float*)d_in[2];
    const float* freq  = (const float*)d_in[3];
    const float* phase = (const float*)d_in[4];
    const float* wpe   = (const float*)d_in[5];
    const float* ln1w  = (const float*)d_in[6];
    const float* ln1b  = (const float*)d_in[7];
    const float* qkvw  = (const float*)d_in[8];
    const float* qkvb  = (const float*)d_in[9];
    const float* projw = (const float*)d_in[10];
    const float* projb = (const float*)d_in[11];
    const float* ln2w  = (const float*)d_in[12];
    const float* ln2b  = (const float*)d_in[13];
    const float* fcw   = (const float*)d_in[14];
    const float* fcb   = (const float*)d_in[15];
    const float* fc2w  = (const float*)d_in[16];
    const float* fc2b  = (const float*)d_in[17];
    const float* lnfw  = (const float*)d_in[18];
    const float* lnfb  = (const float*)d_in[19];
    const float* lmw   = (const float*)d_in[20];
    const float* tpw   = (const float*)d_in[21];
    float* out = (float*)d_out;

    float *x, *h, *qkv, *att, *mid;
    cudaGetSymbolAddress((void**)&x,   g_x);
    cudaGetSymbolAddress((void**)&h,   g_h);
    cudaGetSymbolAddress((void**)&qkv, g_qkv);
    cudaGetSymbolAddress((void**)&att, g_att);
    cudaGetSymbolAddress((void**)&mid, g_mid);

    embed_k<<<MT, 256>>>(idx, ts, wte, freq, phase, wpe, x);

    for (int l = 0; l < Lv; l++) {
        ln_k<<<MT, 256>>>(x, ln1w + l * Cc, ln1b + l * Cc, h);
        gemm_mma<1><<<dim3(C3 / 128, MT / 128), 256>>>(
            h, qkvw + (size_t)l * C3 * Cc, qkvb + l * C3, nullptr, qkv, MT, C3, Cc);
        attn_k<<<dim3(Tv / 128, Bv * Hh), 128>>>(qkv, att);
        gemm_mma<2><<<dim3(Cc / 128, MT / 128), 256>>>(
            att, projw + (size_t)l * Cc * Cc, projb + l * Cc, x, x, MT, Cc, Cc);
        ln_k<<<MT, 256>>>(x, ln2w + l * Cc, ln2b + l * Cc, h);
        gemm_mma<3><<<dim3(C4 / 128, MT / 128), 256>>>(
            h, fcw + (size_t)l * C4 * Cc, fcb + l * C4, nullptr, mid, MT, C4, Cc);
        gemm_mma<2><<<dim3(Cc / 128, MT / 128), 256>>>(
            mid, fc2w + (size_t)l * Cc * C4, fc2b + l * Cc, x, x, MT, Cc, C4);
    }

    ln_k<<<MT, 256>>>(x, lnfw, lnfb, h);
    gemm_mma<0><<<dim3((Vv + 127) / 128, MT / 128), 256>>>(
        h, lmw, nullptr, nullptr, out, MT, Vv, Cc);
    tpred_k<<<MT / 8, 256>>>(h, tpw, out + (size_t)MT * Vv);
}

// round 8
// speedup vs baseline: 1.4036x; 1.4036x over previous
#include <cuda_runtime.h>
#include <cuda_bf16.h>
#include <math.h>
#include <cstdint>

// ---------------- problem constants ----------------
#define Bv   4
#define Tv   1024
#define Lv   12
#define Hh   12
#define Cc   768
#define TE   64
#define WTE  704      // C - TE
#define Vv   10000
#define Dd   64
#define MT   4096     // B*T rows
#define C3   2304     // 3C
#define C4   3072     // 4C

// ---------------- scratch (device globals; no allocs allowed) ----------------
__device__ float g_x  [(size_t)MT * Cc];   // residual stream
__device__ float g_h  [(size_t)MT * Cc];   // LN output
__device__ float g_qkv[(size_t)MT * C3];   // qkv projection
__device__ float g_att[(size_t)MT * Cc];   // attention output
__device__ float g_mid[(size_t)MT * C4];   // MLP hidden

// ---------------- small helpers ----------------
__device__ __forceinline__ uint32_t smaddr(const void* p) {
    uint32_t a;
    asm("{ .reg .u64 t; cvta.to.shared.u64 t, %1; cvt.u32.u64 %0, t; }"
        : "=r"(a) : "l"(p));
    return a;
}

__device__ __forceinline__ void cp16(uint32_t dst, const void* src, int bytes) {
    asm volatile("cp.async.cg.shared.global [%0], [%1], 16, %2;"
                 :: "r"(dst), "l"(src), "r"(bytes));
}

// bf16x3 split: hi = packed truncated-bf16 of (x0,x1), lo = packed bf16(residual).
// Residual x - trunc(x) is exact in fp32; combined scheme captures ~16 mantissa bits.
__device__ __forceinline__ void split_bf16x2(float x0, float x1,
                                             uint32_t& hi, uint32_t& lo) {
    uint32_t u0 = __float_as_uint(x0), u1 = __float_as_uint(x1);
    uint32_t h;
    asm("prmt.b32 %0, %1, %2, 0x7632;" : "=r"(h) : "r"(u0), "r"(u1));
    float r0 = x0 - __uint_as_float(u0 & 0xFFFF0000u);
    float r1 = x1 - __uint_as_float(u1 & 0xFFFF0000u);
    hi = h;
    uint32_t l;
    asm("cvt.rn.bf16x2.f32 %0, %1, %2;" : "=r"(l) : "f"(r1), "f"(r0));
    lo = l;
}

#define MMA16(d, a, b)                                                         \
    asm volatile(                                                              \
        "mma.sync.aligned.m16n8k16.row.col.f32.bf16.bf16.f32 "                 \
        "{%0,%1,%2,%3},{%4,%5,%6,%7},{%8,%9},{%0,%1,%2,%3};"                   \
        : "+f"(d[0]), "+f"(d[1]), "+f"(d[2]), "+f"(d[3])                       \
        : "r"(a[0]), "r"(a[1]), "r"(a[2]), "r"(a[3]), "r"(b[0]), "r"(b[1]))

// ---------------- embedding: x = concat(wte[idx], cos(ts*f+p)) + wpe ----------
__global__ __launch_bounds__(256) void embed_k(
    const int* __restrict__ idx, const float* __restrict__ ts,
    const float* __restrict__ wte, const float* __restrict__ freq,
    const float* __restrict__ phase, const float* __restrict__ wpe,
    float* __restrict__ x)
{
    int rowi = blockIdx.x;           // b*T + t
    int t = rowi & (Tv - 1);
    int token = idx[rowi];
    float tsv = ts[rowi];
    for (int c = threadIdx.x; c < Cc; c += 256) {
        float v;
        if (c < WTE) v = wte[(size_t)token * WTE + c];
        else {
            int e = c - WTE;
            v = cosf(tsv * freq[e] + phase[e]);
        }
        x[(size_t)rowi * Cc + c] = v + wpe[t * Cc + c];
    }
}

// ---------------- layernorm over C=768 ----------------
__global__ __launch_bounds__(256) void ln_k(
    const float* __restrict__ x, const float* __restrict__ w,
    const float* __restrict__ bseg, float* __restrict__ out)
{
    int rowi = blockIdx.x;
    const float* xr = x + (size_t)rowi * Cc;
    int t = threadIdx.x;
    float v[3];
    float s = 0.f, sq = 0.f;
#pragma unroll
    for (int i = 0; i < 3; i++) {
        v[i] = xr[t + i * 256];
        s += v[i];
        sq += v[i] * v[i];
    }
    __shared__ float red[64];
#pragma unroll
    for (int off = 16; off; off >>= 1) {
        s  += __shfl_down_sync(0xffffffffu, s, off);
        sq += __shfl_down_sync(0xffffffffu, sq, off);
    }
    int wid = t >> 5, lane = t & 31;
    if (lane == 0) { red[wid] = s; red[wid + 32] = sq; }
    __syncthreads();
    if (wid == 0) {
        s  = (lane < 8) ? red[lane] : 0.f;
        sq = (lane < 8) ? red[lane + 32] : 0.f;
#pragma unroll
        for (int off = 4; off; off >>= 1) {
            s  += __shfl_down_sync(0xffffffffu, s, off);
            sq += __shfl_down_sync(0xffffffffu, sq, off);
        }
        if (lane == 0) {
            float mu = s * (1.f / Cc);
            float var = sq * (1.f / Cc) - mu * mu;
            red[0] = mu;
            red[1] = rsqrtf(var + 1e-5f);
        }
    }
    __syncthreads();
    float mu = red[0], rstd = red[1];
#pragma unroll
    for (int i = 0; i < 3; i++) {
        int c = t + i * 256;
        out[(size_t)rowi * Cc + c] = (v[i] - mu) * rstd * w[c] + bseg[c];
    }
}

// ---------------- bf16x3 tensor-core GEMM: out[M,N] = A[M,K] @ W[N,K]^T (+epi)
// EPI: 0 = none, 1 = +bias, 2 = +bias+residual, 3 = +bias then exact GELU
// Block tile 128x128, K-chunk 16, 256 threads = 8 warps in 2(M) x 4(N),
// warp tile 64x32. cp.async double buffer. SROW=24 -> LDS.64 conflict-free.
#define SROW 24

template <int EPI>
__global__ __launch_bounds__(256, 1) void gemm_mma(
    const float* __restrict__ A, const float* __restrict__ W,
    const float* __restrict__ bias, const float* __restrict__ resid,
    float* __restrict__ out, int M, int N, int K)
{
    __shared__ float sA[2][128 * SROW];
    __shared__ float sB[2][128 * SROW];
    int tid  = threadIdx.x;
    int warp = tid >> 5, lane = tid & 31;
    int warpM = warp >> 2, warpN = warp & 3;   // 2 x 4 warps
    int grp = lane >> 2, tig = lane & 3;
    int m0 = blockIdx.y * 128, n0 = blockIdx.x * 128;

    float acc[4][4][4];
#pragma unroll
    for (int i = 0; i < 4; i++)
#pragma unroll
        for (int j = 0; j < 4; j++)
#pragma unroll
            for (int r = 0; r < 4; r++) acc[i][j][r] = 0.f;

    int nC = K >> 4;   // K-chunks of 16

    // ---- stage chunk 0 ----
    {
        uint32_t da = smaddr(&sA[0][0]);
        uint32_t db = smaddr(&sB[0][0]);
#pragma unroll
        for (int j = 0; j < 2; j++) {
            int idx = tid + j * 256;
            int r = idx >> 2, kq = (idx & 3) * 4;
            cp16(da + (r * SROW + kq) * 4,
                 A + (size_t)(m0 + r) * K + kq, 16);
            int n = n0 + r;
            const float* src = W + (size_t)(n < N ? n : N - 1) * K + kq;
            cp16(db + (r * SROW + kq) * 4, src, n < N ? 16 : 0);
        }
        asm volatile("cp.async.commit_group;");
    }

    for (int c = 0; c < nC; ++c) {
        asm volatile("cp.async.wait_group 0;");
        __syncthreads();
        if (c + 1 < nC) {
            int k0 = (c + 1) << 4;
            int buf = (c + 1) & 1;
            uint32_t da = smaddr(&sA[buf][0]);
            uint32_t db = smaddr(&sB[buf][0]);
#pragma unroll
            for (int j = 0; j < 2; j++) {
                int idx = tid + j * 256;
                int r = idx >> 2, kq = (idx & 3) * 4;
                cp16(da + (r * SROW + kq) * 4,
                     A + (size_t)(m0 + r) * K + k0 + kq, 16);
                int n = n0 + r;
                const float* src = W + (size_t)(n < N ? n : N - 1) * K + k0 + kq;
                cp16(db + (r * SROW + kq) * 4, src, n < N ? 16 : 0);
            }
            asm volatile("cp.async.commit_group;");
        }
        const float* As = sA[c & 1];
        const float* Bs = sB[c & 1];

        uint32_t ah[4][4], al[4][4], bh[4][2], bl[4][2];
#pragma unroll
        for (int nt = 0; nt < 4; nt++) {
            int n = warpN * 32 + nt * 8 + grp;
            float2 p0 = *(const float2*)&Bs[n * SROW + 2 * tig];
            float2 p1 = *(const float2*)&Bs[n * SROW + 2 * tig + 8];
            split_bf16x2(p0.x, p0.y, bh[nt][0], bl[nt][0]);
            split_bf16x2(p1.x, p1.y, bh[nt][1], bl[nt][1]);
        }
#pragma unroll
        for (int mt = 0; mt < 4; mt++) {
            int m = warpM * 64 + mt * 16 + grp;
            float2 q0 = *(const float2*)&As[m * SROW + 2 * tig];
            float2 q1 = *(const float2*)&As[(m + 8) * SROW + 2 * tig];
            float2 q2 = *(const float2*)&As[m * SROW + 2 * tig + 8];
            float2 q3 = *(const float2*)&As[(m + 8) * SROW + 2 * tig + 8];
            split_bf16x2(q0.x, q0.y, ah[mt][0], al[mt][0]);
            split_bf16x2(q1.x, q1.y, ah[mt][1], al[mt][1]);
            split_bf16x2(q2.x, q2.y, ah[mt][2], al[mt][2]);
            split_bf16x2(q3.x, q3.y, ah[mt][3], al[mt][3]);
        }
#pragma unroll
        for (int mt = 0; mt < 4; mt++)
#pragma unroll
            for (int nt = 0; nt < 4; nt++) {
                MMA16(acc[mt][nt], ah[mt], bh[nt]);
                MMA16(acc[mt][nt], ah[mt], bl[nt]);
                MMA16(acc[mt][nt], al[mt], bh[nt]);
            }
        __syncthreads();
    }

    // ---- epilogue ----
#pragma unroll
    for (int mt = 0; mt < 4; mt++) {
        int row = m0 + warpM * 64 + mt * 16 + grp;
#pragma unroll
        for (int nt = 0; nt < 4; nt++) {
            int col = n0 + warpN * 32 + nt * 8 + tig * 2;
#pragma unroll
            for (int r = 0; r < 4; r++) {
                int mm = row + (r >= 2 ? 8 : 0);
                int nn = col + (r & 1);
                if (nn >= N) continue;
                float v = acc[mt][nt][r];
                if (EPI >= 1) v += bias[nn];
                if (EPI == 2) v += resid[(size_t)mm * N + nn];
                if (EPI == 3) v = 0.5f * v * (1.0f + erff(v * 0.70710678118f));
                out[(size_t)mm * N + nn] = v;
            }
        }
    }
}

// ---------------- fused causal flash attention ----------------
// grid: (T/128, B*H), block: 128 threads; one query per thread.
// log2-domain scores (q pre-scaled); 4 independent dot partials for ILP.
__global__ __launch_bounds__(128) void attn_k(
    const float* __restrict__ qkv, float* __restrict__ y)
{
    int bh = blockIdx.y;
    int b = bh / Hh, h = bh % Hh;
    int q0 = blockIdx.x * 128;
    int qi = q0 + threadIdx.x;
    __shared__ float Ks[64][64];
    __shared__ float Vs[64][64];
    const float qscale = 0.125f * 1.4426950408889634f;   // (1/sqrt(64)) * log2(e)

    float q[64];
    const float* qrow = &qkv[(size_t)(b * Tv + qi) * C3 + h * Dd];
#pragma unroll
    for (int i = 0; i < 16; i++) {
        float4 v = *(const float4*)&qrow[i * 4];
        q[i*4]   = v.x * qscale; q[i*4+1] = v.y * qscale;
        q[i*4+2] = v.z * qscale; q[i*4+3] = v.w * qscale;
    }
    float o[64];
#pragma unroll
    for (int d = 0; d < 64; d++) o[d] = 0.f;
    float mx = -1e30f, l = 0.f;

    int jmax = (q0 + 127) >> 6;            // inclusive key-tile bound
    int row = threadIdx.x >> 1, half = (threadIdx.x & 1) * 32;

    for (int j = 0; j <= jmax; j++) {
        const float* kbase = &qkv[(size_t)(b * Tv + j * 64 + row) * C3 + Cc + h * Dd + half];
        const float* vbase = kbase + Cc;   // V is one C further
#pragma unroll
        for (int i = 0; i < 8; i++) {
            *(float4*)&Ks[row][half + i * 4] = *(const float4*)&kbase[i * 4];
            *(float4*)&Vs[row][half + i * 4] = *(const float4*)&vbase[i * 4];
        }
        __syncthreads();
        int kend = min(64, qi - j * 64 + 1);   // causal limit inside tile
        for (int kk = 0; kk < kend; kk++) {
            // 4 independent partial dot-products (breaks the serial chain)
            float s0 = 0.f, s1 = 0.f, s2 = 0.f, s3 = 0.f;
            const float4* K4 = (const float4*)&Ks[kk][0];
#pragma unroll
            for (int i = 0; i < 4; i++) {
                float4 k0 = K4[i];
                s0 += q[i*4]    * k0.x + q[i*4+1]  * k0.y + q[i*4+2]  * k0.z + q[i*4+3]  * k0.w;
                float4 k1 = K4[i+4];
                s1 += q[16+i*4] * k1.x + q[17+i*4] * k1.y + q[18+i*4] * k1.z + q[19+i*4] * k1.w;
                float4 k2 = K4[i+8];
                s2 += q[32+i*4] * k2.x + q[33+i*4] * k2.y + q[34+i*4] * k2.z + q[35+i*4] * k2.w;
                float4 k3 = K4[i+12];
                s3 += q[48+i*4] * k3.x + q[49+i*4] * k3.y + q[50+i*4] * k3.z + q[51+i*4] * k3.w;
            }
            float s = (s0 + s1) + (s2 + s3);   // log2 domain
            if (s > mx) {
                float c = exp2f(mx - s);
                mx = s;
                l *= c;
#pragma unroll
                for (int d = 0; d < 64; d++) o[d] *= c;
            }
            float p = exp2f(s - mx);
            l += p;
            const float4* V4 = (const float4*)&Vs[kk][0];
#pragma unroll
            for (int i = 0; i < 16; i++) {
                float4 vv = V4[i];
                o[i*4]   += p * vv.x; o[i*4+1] += p * vv.y;
                o[i*4+2] += p * vv.z; o[i*4+3] += p * vv.w;
            }
        }
        __syncthreads();
    }
    float inv = 1.f / l;
    float* orow = &y[(size_t)(b * Tv + qi) * Cc + h * Dd];
#pragma unroll
    for (int d = 0; d < 64; d++) orow[d] = o[d] * inv;
}

// ---------------- tpred: out[m] = dot(h[m,:], tp_w) ----------------
__global__ __launch_bounds__(256) void tpred_k(
    const float* __restrict__ hbuf, const float* __restrict__ tpw,
    float* __restrict__ out)
{
    int rowi = blockIdx.x * 8 + (threadIdx.x >> 5);
    int lane = threadIdx.x & 31;
    const float* xr = hbuf + (size_t)rowi * Cc;
    float s = 0.f;
#pragma unroll
    for (int i = lane; i < Cc; i += 32) s += xr[i] * tpw[i];
#pragma unroll
    for (int off = 16; off; off >>= 1) s += __shfl_down_sync(0xffffffffu, s, off);
    if (lane == 0) out[rowi] = s;
}

// ---------------- launch ----------------
extern "C" void kernel_launch(void* const* d_in, const int* in_sizes, int n_in,
                              void* d_out, int out_size)
{
    (void)in_sizes; (void)n_in; (void)out_size;
    const int*   idx   = (const int*)  d_in[0];
    const float* ts    = (const float*)d_in[1];
    const float* wte   = (const float*)d_in[2];
    const float* freq  = (const float*)d_in[3];
    const float* phase = (const float*)d_in[4];
    const float* wpe   = (const float*)d_in[5];
    const float* ln1w  = (const float*)d_in[6];
    const float* ln1b  = (const float*)d_in[7];
    const float* qkvw  = (const float*)d_in[8];
    const float* qkvb  = (const float*)d_in[9];
    const float* projw = (const float*)d_in[10];
    const float* projb = (const float*)d_in[11];
    const float* ln2w  = (const float*)d_in[12];
    const float* ln2b  = (const float*)d_in[13];
    const float* fcw   = (const float*)d_in[14];
    const float* fcb   = (const float*)d_in[15];
    const float* fc2w  = (const float*)d_in[16];
    const float* fc2b  = (const float*)d_in[17];
    const float* lnfw  = (const float*)d_in[18];
    const float* lnfb  = (const float*)d_in[19];
    const float* lmw   = (const float*)d_in[20];
    const float* tpw   = (const float*)d_in[21];
    float* out = (float*)d_out;

    float *x, *h, *qkv, *att, *mid;
    cudaGetSymbolAddress((void**)&x,   g_x);
    cudaGetSymbolAddress((void**)&h,   g_h);
    cudaGetSymbolAddress((void**)&qkv, g_qkv);
    cudaGetSymbolAddress((void**)&att, g_att);
    cudaGetSymbolAddress((void**)&mid, g_mid);

    embed_k<<<MT, 256>>>(idx, ts, wte, freq, phase, wpe, x);

    for (int l = 0; l < Lv; l++) {
        ln_k<<<MT, 256>>>(x, ln1w + l * Cc, ln1b + l * Cc, h);
        gemm_mma<1><<<dim3(C3 / 128, MT / 128), 256>>>(
            h, qkvw + (size_t)l * C3 * Cc, qkvb + l * C3, nullptr, qkv, MT, C3, Cc);
        attn_k<<<dim3(Tv / 128, Bv * Hh), 128>>>(qkv, att);
        gemm_mma<2><<<dim3(Cc / 128, MT / 128), 256>>>(
            att, projw + (size_t)l * Cc * Cc, projb + l * Cc, x, x, MT, Cc, Cc);
        ln_k<<<MT, 256>>>(x, ln2w + l * Cc, ln2b + l * Cc, h);
        gemm_mma<3><<<dim3(C4 / 128, MT / 128), 256>>>(
            h, fcw + (size_t)l * C4 * Cc, fcb + l * C4, nullptr, mid, MT, C4, Cc);
        gemm_mma<2><<<dim3(Cc / 128, MT / 128), 256>>>(
            mid, fc2w + (size_t)l * Cc * C4, fc2b + l * Cc, x, x, MT, Cc, C4);
    }

    ln_k<<<MT, 256>>>(x, lnfw, lnfb, h);
    gemm_mma<0><<<dim3((Vv + 127) / 128, MT / 128), 256>>>(
        h, lmw, nullptr, nullptr, out, MT, Vv, Cc);
    tpred_k<<<MT / 8, 256>>>(h, tpw, out + (size_t)MT * Vv);
}